// round 7
// baseline (speedup 1.0000x reference)
#include <cuda_runtime.h>
#include <cstdint>
#include <cstddef>

// ---------------------------------------------------------------------------
// Swin Transformer block, B=32 H=W=56 C=384 NH=12 WS=7 SS=3
//   M = B*H*W = 100352 token rows, N=49 tokens/window, NW=64 windows/img
// Pipeline:
//   1) LN1 + roll(-3,-3) + window partition          -> g_ywin   (M,384)
//   2) SGEMM  g_ywin @ qkv_w + qkv_b                 -> g_qkv    (M,1152)
//   3) attention per (window,head): bias+mask+softmax-> g_attn   (M,384)
//   4) SGEMM  g_attn @ proj_w + proj_b, scatter
//      (window reverse + roll(+3,+3)) + residual x   -> d_out    (M,384)
//   5) LN2 on d_out                                  -> g_ywin   (reuse)
//   6) SGEMM  g_ywin @ fc1_w + fc1_b, GELU           -> g_h      (M,1536)
//   7) SGEMM  g_h @ fc2_w + fc2_b, GELU, += d_out    -> d_out
// ---------------------------------------------------------------------------

#define M_ROWS 100352
#define CDIM   384
#define NHEADS 12
#define HD     32
#define NWIN   64      // windows per image (8x8)
#define NTOK   49      // tokens per window

// Scratch (device globals: allocation inside kernel_launch is forbidden)
__device__ float g_ywin[(size_t)M_ROWS * 384];    // 154 MB (reused for LN2 out)
__device__ float g_qkv [(size_t)M_ROWS * 1152];   // 462 MB
__device__ float g_attn[(size_t)M_ROWS * 384];    // 154 MB
__device__ float g_h   [(size_t)M_ROWS * 1536];   // 616 MB

__device__ __forceinline__ float gelu_exact(float x) {
    return 0.5f * x * (1.0f + erff(x * 0.70710678118654752f));
}

// ---------------------------------------------------------------------------
// LayerNorm, one warp per row. SHIFT=true: gather from rolled+windowed source.
// window-order row m -> (b, win, n); rolled pos (ih,iw); source (ih+3,iw+3)%56
// ---------------------------------------------------------------------------
template <bool SHIFT>
__global__ void __launch_bounds__(256) ln_kernel(
    const float* __restrict__ x, const float* __restrict__ g,
    const float* __restrict__ b, float* __restrict__ out)
{
    int row  = blockIdx.x * 8 + (threadIdx.x >> 5);
    int lane = threadIdx.x & 31;

    const float* src;
    if (SHIFT) {
        int bb  = row / 3136;  int rr = row - bb * 3136;
        int win = rr / NTOK;   int n  = rr - win * NTOK;
        int ih  = (win >> 3) * 7 + n / 7;
        int iw  = (win & 7) * 7 + n % 7;
        int h = ih + 3; if (h >= 56) h -= 56;
        int w = iw + 3; if (w >= 56) w -= 56;
        src = x + ((size_t)bb * 3136 + h * 56 + w) * CDIM;
    } else {
        src = x + (size_t)row * CDIM;
    }

    float vals[12];
    float s = 0.f;
#pragma unroll
    for (int i = 0; i < 12; i++) { vals[i] = src[lane + 32 * i]; s += vals[i]; }
#pragma unroll
    for (int o = 16; o; o >>= 1) s += __shfl_xor_sync(0xffffffffu, s, o);
    float mean = s * (1.0f / 384.0f);

    float vs = 0.f;
#pragma unroll
    for (int i = 0; i < 12; i++) { float d = vals[i] - mean; vs += d * d; }
#pragma unroll
    for (int o = 16; o; o >>= 1) vs += __shfl_xor_sync(0xffffffffu, vs, o);
    float rstd = rsqrtf(vs * (1.0f / 384.0f) + 1e-5f);

    float* dst = out + (size_t)row * CDIM;
#pragma unroll
    for (int i = 0; i < 12; i++) {
        int c = lane + 32 * i;
        dst[c] = (vals[i] - mean) * rstd * g[c] + b[c];
    }
}

// ---------------------------------------------------------------------------
// Attention: one CTA per (window, head). N=49, HD=32.
// S = (q*scale) k^T + rel_bias + shift_mask ; softmax ; O = S v
// rel index = (di+6)*13 + (dj+6); region code boundaries at rows 49 / 53.
// ---------------------------------------------------------------------------
__global__ void __launch_bounds__(256) attn_kernel(
    const float* __restrict__ qkv, const float* __restrict__ rel_bias,
    float* __restrict__ out)
{
    __shared__ float q[NTOK][33], k[NTOK][33], v[NTOK][33];
    __shared__ float S[NTOK][50];
    __shared__ int   code[NTOK];

    const int win  = blockIdx.x;
    const int head = blockIdx.y;
    const int tid  = threadIdx.x;
    const size_t base = (size_t)win * NTOK * 1152 + head * HD;
    const float scale = 0.17677669529663687f;  // 1/sqrt(32)

    for (int e = tid; e < NTOK * HD; e += 256) {
        int n = e >> 5, d = e & 31;
        size_t o = base + (size_t)n * 1152 + d;
        q[n][d] = qkv[o] * scale;
        k[n][d] = qkv[o + 384];
        v[n][d] = qkv[o + 768];
    }
    if (tid < NTOK) {
        int wib = win & 63;                 // window index within image
        int gh = (wib >> 3) * 7 + tid / 7;  // position in shifted image
        int gw = (wib & 7) * 7 + tid % 7;
        int hc = (gh < 49) ? 0 : (gh < 53 ? 1 : 2);
        int wc = (gw < 49) ? 0 : (gw < 53 ? 1 : 2);
        code[tid] = hc * 3 + wc;
    }
    __syncthreads();

    for (int e = tid; e < NTOK * NTOK; e += 256) {
        int i = e / NTOK, j = e - i * NTOK;
        float acc = 0.f;
#pragma unroll
        for (int d = 0; d < HD; d++) acc += q[i][d] * k[j][d];
        int ridx = (i / 7 - j / 7 + 6) * 13 + (i % 7 - j % 7 + 6);
        acc += rel_bias[ridx * NHEADS + head];
        if (code[i] != code[j]) acc -= 100.0f;
        S[i][j] = acc;
    }
    __syncthreads();

    int warp = tid >> 5, lane = tid & 31;
    for (int row = warp; row < NTOK; row += 8) {
        float v1 = S[row][lane];
        float v2 = (lane < 17) ? S[row][lane + 32] : -1e30f;
        float mx = fmaxf(v1, v2);
#pragma unroll
        for (int o = 16; o; o >>= 1) mx = fmaxf(mx, __shfl_xor_sync(0xffffffffu, mx, o));
        float e1 = __expf(v1 - mx);
        float e2 = (lane < 17) ? __expf(v2 - mx) : 0.f;
        float sm = e1 + e2;
#pragma unroll
        for (int o = 16; o; o >>= 1) sm += __shfl_xor_sync(0xffffffffu, sm, o);
        float inv = 1.0f / sm;
        S[row][lane] = e1 * inv;
        if (lane < 17) S[row][lane + 32] = e2 * inv;
    }
    __syncthreads();

    for (int e = tid; e < NTOK * HD; e += 256) {
        int i = e >> 5, d = e & 31;
        float acc = 0.f;
#pragma unroll
        for (int j = 0; j < NTOK; j++) acc += S[i][j] * v[j][d];
        out[((size_t)win * NTOK + i) * CDIM + head * HD + d] = acc;
    }
}

// ---------------------------------------------------------------------------
// SGEMM: C(M,N) = A(M,K) @ B(K,N) + bias, 128x128x16 tile, 8x8 per thread.
// All dims divisible by tile sizes (M=100352, N in {384,1152,1536}, K in
// {384,1536}), so no bounds checks.
// MODE 0: C = A@B + bias
// MODE 1: d_out[scatter(r)] = X[scatter(r)] + A@B + bias   (proj + residual,
//         scatter = window reverse + roll(+3,+3))
// MODE 2: C = gelu(A@B + bias)
// MODE 3: C += gelu(A@B + bias)
// ---------------------------------------------------------------------------
template <int MODE>
__global__ void __launch_bounds__(256) sgemm_kernel(
    const float* __restrict__ A, const float* __restrict__ Bm,
    const float* __restrict__ bias, float* __restrict__ C,
    const float* __restrict__ X, int M, int N, int K)
{
    constexpr int BM = 128, BN = 128, BK = 16;
    __shared__ float As[BK][BM];
    __shared__ float Bs[BK][BN];

    const int tid = threadIdx.x;
    const int tx = tid % 16, ty = tid / 16;
    const int rowBase = blockIdx.y * BM;
    const int colBase = blockIdx.x * BN;

    const int aRow = tid >> 2;          // 0..63
    const int aCol = (tid & 3) * 4;     // 0,4,8,12
    const int bRow = tid >> 5;          // 0..7
    const int bCol = (tid & 31) * 4;    // 0..124

    float acc[8][8];
#pragma unroll
    for (int i = 0; i < 8; i++)
#pragma unroll
        for (int j = 0; j < 8; j++) acc[i][j] = 0.f;

    for (int k0 = 0; k0 < K; k0 += BK) {
#pragma unroll
        for (int it = 0; it < 2; it++) {
            float4 va = *(const float4*)(A + (size_t)(rowBase + aRow + it * 64) * K + k0 + aCol);
            As[aCol + 0][aRow + it * 64] = va.x;
            As[aCol + 1][aRow + it * 64] = va.y;
            As[aCol + 2][aRow + it * 64] = va.z;
            As[aCol + 3][aRow + it * 64] = va.w;
        }
#pragma unroll
        for (int it = 0; it < 2; it++) {
            *(float4*)&Bs[bRow + it * 8][bCol] =
                *(const float4*)(Bm + (size_t)(k0 + bRow + it * 8) * N + colBase + bCol);
        }
        __syncthreads();

#pragma unroll
        for (int kk = 0; kk < BK; kk++) {
            float ra[8], rb[8];
#pragma unroll
            for (int i = 0; i < 8; i++) ra[i] = As[kk][ty * 8 + i];
#pragma unroll
            for (int j = 0; j < 8; j++) rb[j] = Bs[kk][tx * 8 + j];
#pragma unroll
            for (int i = 0; i < 8; i++)
#pragma unroll
                for (int j = 0; j < 8; j++) acc[i][j] += ra[i] * rb[j];
        }
        __syncthreads();
    }

    const int r0 = rowBase + ty * 8;
    const int c0 = colBase + tx * 8;
#pragma unroll
    for (int i = 0; i < 8; i++) {
        int r = r0 + i;
        size_t dstRow;
        if (MODE == 1) {
            int bb  = r / 3136;  int rr = r - bb * 3136;
            int win = rr / NTOK; int n  = rr - win * NTOK;
            int ih  = (win >> 3) * 7 + n / 7;
            int iw  = (win & 7) * 7 + n % 7;
            int h = ih + 3; if (h >= 56) h -= 56;
            int w = iw + 3; if (w >= 56) w -= 56;
            dstRow = ((size_t)bb * 3136 + h * 56 + w) * (size_t)N;
        } else {
            dstRow = (size_t)r * (size_t)N;
        }
#pragma unroll
        for (int j = 0; j < 8; j += 4) {
            int c = c0 + j;
            float4 bv = *(const float4*)(bias + c);
            float4 o;
            o.x = acc[i][j + 0] + bv.x;
            o.y = acc[i][j + 1] + bv.y;
            o.z = acc[i][j + 2] + bv.z;
            o.w = acc[i][j + 3] + bv.w;
            if (MODE == 1) {
                float4 xv = *(const float4*)(X + dstRow + c);
                o.x += xv.x; o.y += xv.y; o.z += xv.z; o.w += xv.w;
            }
            if (MODE == 2) {
                o.x = gelu_exact(o.x); o.y = gelu_exact(o.y);
                o.z = gelu_exact(o.z); o.w = gelu_exact(o.w);
            }
            if (MODE == 3) {
                float4 cv = *(const float4*)(C + dstRow + c);
                o.x = cv.x + gelu_exact(o.x);
                o.y = cv.y + gelu_exact(o.y);
                o.z = cv.z + gelu_exact(o.z);
                o.w = cv.w + gelu_exact(o.w);
            }
            *(float4*)(C + dstRow + c) = o;
        }
    }
}

// ---------------------------------------------------------------------------
extern "C" void kernel_launch(void* const* d_in, const int* in_sizes, int n_in,
                              void* d_out, int out_size)
{
    (void)in_sizes; (void)n_in; (void)out_size;

    const float* x     = (const float*)d_in[0];
    const float* ln1g  = (const float*)d_in[1];
    const float* ln1b  = (const float*)d_in[2];
    const float* qkvw  = (const float*)d_in[3];
    const float* qkvb  = (const float*)d_in[4];
    const float* relb  = (const float*)d_in[5];
    const float* projw = (const float*)d_in[6];
    const float* projb = (const float*)d_in[7];
    const float* ln2g  = (const float*)d_in[8];
    const float* ln2b  = (const float*)d_in[9];
    const float* fc1w  = (const float*)d_in[10];
    const float* fc1b  = (const float*)d_in[11];
    const float* fc2w  = (const float*)d_in[12];
    const float* fc2b  = (const float*)d_in[13];
    float* out = (float*)d_out;

    float *ywin, *qkv, *attn, *hbuf;
    cudaGetSymbolAddress((void**)&ywin, g_ywin);
    cudaGetSymbolAddress((void**)&qkv,  g_qkv);
    cudaGetSymbolAddress((void**)&attn, g_attn);
    cudaGetSymbolAddress((void**)&hbuf, g_h);

    // 1) LN1 + shift + window partition
    ln_kernel<true><<<M_ROWS / 8, 256>>>(x, ln1g, ln1b, ywin);

    // 2) QKV GEMM: (100352,384)@(384,1152)
    sgemm_kernel<0><<<dim3(1152 / 128, M_ROWS / 128), 256>>>(
        ywin, qkvw, qkvb, qkv, nullptr, M_ROWS, 1152, 384);

    // 3) windowed attention
    attn_kernel<<<dim3(M_ROWS / NTOK, NHEADS), 256>>>(qkv, relb, attn);

    // 4) proj GEMM + window reverse + roll back + residual  -> d_out = x1
    sgemm_kernel<1><<<dim3(384 / 128, M_ROWS / 128), 256>>>(
        attn, projw, projb, out, x, M_ROWS, 384, 384);

    // 5) LN2 (reads d_out, reuses ywin scratch)
    ln_kernel<false><<<M_ROWS / 8, 256>>>(out, ln2g, ln2b, ywin);

    // 6) FC1 GEMM + exact GELU: (100352,384)@(384,1536)
    sgemm_kernel<2><<<dim3(1536 / 128, M_ROWS / 128), 256>>>(
        ywin, fc1w, fc1b, hbuf, nullptr, M_ROWS, 1536, 384);

    // 7) FC2 GEMM + exact GELU + residual accumulate into d_out
    sgemm_kernel<3><<<dim3(384 / 128, M_ROWS / 128), 256>>>(
        hbuf, fc2w, fc2b, out, nullptr, M_ROWS, 384, 1536);
}

// round 8
// speedup vs baseline: 1.0001x; 1.0001x over previous
#include <cuda_runtime.h>
#include <cstdint>
#include <cstddef>

// ---------------------------------------------------------------------------
// Swin Transformer block, B=32 H=W=56 C=384 NH=12 WS=7 SS=3
//   M = B*H*W = 100352 token rows, N=49 tokens/window, NW=64 windows/img
// Pipeline:
//   1) LN1 + roll(-3,-3) + window partition          -> g_ywin   (M,384)
//   2) SGEMM  g_ywin @ qkv_w + qkv_b                 -> g_qkv    (M,1152)
//   3) attention per (window,head): bias+mask+softmax-> g_attn   (M,384)
//   4) SGEMM  g_attn @ proj_w + proj_b, scatter
//      (window reverse + roll(+3,+3)) + residual x   -> d_out    (M,384)
//   5) LN2 on d_out                                  -> g_ywin   (reuse)
//   6) SGEMM  g_ywin @ fc1_w + fc1_b, GELU           -> g_h      (M,1536)
//   7) SGEMM  g_h @ fc2_w + fc2_b, GELU, += d_out    -> d_out
// ---------------------------------------------------------------------------

#define M_ROWS 100352
#define CDIM   384
#define NHEADS 12
#define HD     32
#define NWIN   64      // windows per image (8x8)
#define NTOK   49      // tokens per window

// Scratch (device globals: allocation inside kernel_launch is forbidden)
__device__ float g_ywin[(size_t)M_ROWS * 384];    // 154 MB (reused for LN2 out)
__device__ float g_qkv [(size_t)M_ROWS * 1152];   // 462 MB
__device__ float g_attn[(size_t)M_ROWS * 384];    // 154 MB
__device__ float g_h   [(size_t)M_ROWS * 1536];   // 616 MB

__device__ __forceinline__ float gelu_exact(float x) {
    return 0.5f * x * (1.0f + erff(x * 0.70710678118654752f));
}

// ---------------------------------------------------------------------------
// LayerNorm, one warp per row. SHIFT=true: gather from rolled+windowed source.
// window-order row m -> (b, win, n); rolled pos (ih,iw); source (ih+3,iw+3)%56
// ---------------------------------------------------------------------------
template <bool SHIFT>
__global__ void __launch_bounds__(256) ln_kernel(
    const float* __restrict__ x, const float* __restrict__ g,
    const float* __restrict__ b, float* __restrict__ out)
{
    int row  = blockIdx.x * 8 + (threadIdx.x >> 5);
    int lane = threadIdx.x & 31;

    const float* src;
    if (SHIFT) {
        int bb  = row / 3136;  int rr = row - bb * 3136;
        int win = rr / NTOK;   int n  = rr - win * NTOK;
        int ih  = (win >> 3) * 7 + n / 7;
        int iw  = (win & 7) * 7 + n % 7;
        int h = ih + 3; if (h >= 56) h -= 56;
        int w = iw + 3; if (w >= 56) w -= 56;
        src = x + ((size_t)bb * 3136 + h * 56 + w) * CDIM;
    } else {
        src = x + (size_t)row * CDIM;
    }

    float vals[12];
    float s = 0.f;
#pragma unroll
    for (int i = 0; i < 12; i++) { vals[i] = src[lane + 32 * i]; s += vals[i]; }
#pragma unroll
    for (int o = 16; o; o >>= 1) s += __shfl_xor_sync(0xffffffffu, s, o);
    float mean = s * (1.0f / 384.0f);

    float vs = 0.f;
#pragma unroll
    for (int i = 0; i < 12; i++) { float d = vals[i] - mean; vs += d * d; }
#pragma unroll
    for (int o = 16; o; o >>= 1) vs += __shfl_xor_sync(0xffffffffu, vs, o);
    float rstd = rsqrtf(vs * (1.0f / 384.0f) + 1e-5f);

    float* dst = out + (size_t)row * CDIM;
#pragma unroll
    for (int i = 0; i < 12; i++) {
        int c = lane + 32 * i;
        dst[c] = (vals[i] - mean) * rstd * g[c] + b[c];
    }
}

// ---------------------------------------------------------------------------
// Attention: one CTA per (window, head). N=49, HD=32.
// S = (q*scale) k^T + rel_bias + shift_mask ; softmax ; O = S v
// rel index = (di+6)*13 + (dj+6); region code boundaries at rows 49 / 53.
// ---------------------------------------------------------------------------
__global__ void __launch_bounds__(256) attn_kernel(
    const float* __restrict__ qkv, const float* __restrict__ rel_bias,
    float* __restrict__ out)
{
    __shared__ float q[NTOK][33], k[NTOK][33], v[NTOK][33];
    __shared__ float S[NTOK][50];
    __shared__ int   code[NTOK];

    const int win  = blockIdx.x;
    const int head = blockIdx.y;
    const int tid  = threadIdx.x;
    const size_t base = (size_t)win * NTOK * 1152 + head * HD;
    const float scale = 0.17677669529663687f;  // 1/sqrt(32)

    for (int e = tid; e < NTOK * HD; e += 256) {
        int n = e >> 5, d = e & 31;
        size_t o = base + (size_t)n * 1152 + d;
        q[n][d] = qkv[o] * scale;
        k[n][d] = qkv[o + 384];
        v[n][d] = qkv[o + 768];
    }
    if (tid < NTOK) {
        int wib = win & 63;                 // window index within image
        int gh = (wib >> 3) * 7 + tid / 7;  // position in shifted image
        int gw = (wib & 7) * 7 + tid % 7;
        int hc = (gh < 49) ? 0 : (gh < 53 ? 1 : 2);
        int wc = (gw < 49) ? 0 : (gw < 53 ? 1 : 2);
        code[tid] = hc * 3 + wc;
    }
    __syncthreads();

    for (int e = tid; e < NTOK * NTOK; e += 256) {
        int i = e / NTOK, j = e - i * NTOK;
        float acc = 0.f;
#pragma unroll
        for (int d = 0; d < HD; d++) acc += q[i][d] * k[j][d];
        int ridx = (i / 7 - j / 7 + 6) * 13 + (i % 7 - j % 7 + 6);
        acc += rel_bias[ridx * NHEADS + head];
        if (code[i] != code[j]) acc -= 100.0f;
        S[i][j] = acc;
    }
    __syncthreads();

    int warp = tid >> 5, lane = tid & 31;
    for (int row = warp; row < NTOK; row += 8) {
        float v1 = S[row][lane];
        float v2 = (lane < 17) ? S[row][lane + 32] : -1e30f;
        float mx = fmaxf(v1, v2);
#pragma unroll
        for (int o = 16; o; o >>= 1) mx = fmaxf(mx, __shfl_xor_sync(0xffffffffu, mx, o));
        float e1 = __expf(v1 - mx);
        float e2 = (lane < 17) ? __expf(v2 - mx) : 0.f;
        float sm = e1 + e2;
#pragma unroll
        for (int o = 16; o; o >>= 1) sm += __shfl_xor_sync(0xffffffffu, sm, o);
        float inv = 1.0f / sm;
        S[row][lane] = e1 * inv;
        if (lane < 17) S[row][lane + 32] = e2 * inv;
    }
    __syncthreads();

    for (int e = tid; e < NTOK * HD; e += 256) {
        int i = e >> 5, d = e & 31;
        float acc = 0.f;
#pragma unroll
        for (int j = 0; j < NTOK; j++) acc += S[i][j] * v[j][d];
        out[((size_t)win * NTOK + i) * CDIM + head * HD + d] = acc;
    }
}

// ---------------------------------------------------------------------------
// SGEMM: C(M,N) = A(M,K) @ B(K,N) + bias, 128x128x16 tile, 8x8 per thread.
// All dims divisible by tile sizes (M=100352, N in {384,1152,1536}, K in
// {384,1536}), so no bounds checks.
// MODE 0: C = A@B + bias
// MODE 1: d_out[scatter(r)] = X[scatter(r)] + A@B + bias   (proj + residual,
//         scatter = window reverse + roll(+3,+3))
// MODE 2: C = gelu(A@B + bias)
// MODE 3: C += gelu(A@B + bias)
// ---------------------------------------------------------------------------
template <int MODE>
__global__ void __launch_bounds__(256) sgemm_kernel(
    const float* __restrict__ A, const float* __restrict__ Bm,
    const float* __restrict__ bias, float* __restrict__ C,
    const float* __restrict__ X, int M, int N, int K)
{
    constexpr int BM = 128, BN = 128, BK = 16;
    __shared__ float As[BK][BM];
    __shared__ float Bs[BK][BN];

    const int tid = threadIdx.x;
    const int tx = tid % 16, ty = tid / 16;
    const int rowBase = blockIdx.y * BM;
    const int colBase = blockIdx.x * BN;

    const int aRow = tid >> 2;          // 0..63
    const int aCol = (tid & 3) * 4;     // 0,4,8,12
    const int bRow = tid >> 5;          // 0..7
    const int bCol = (tid & 31) * 4;    // 0..124

    float acc[8][8];
#pragma unroll
    for (int i = 0; i < 8; i++)
#pragma unroll
        for (int j = 0; j < 8; j++) acc[i][j] = 0.f;

    for (int k0 = 0; k0 < K; k0 += BK) {
#pragma unroll
        for (int it = 0; it < 2; it++) {
            float4 va = *(const float4*)(A + (size_t)(rowBase + aRow + it * 64) * K + k0 + aCol);
            As[aCol + 0][aRow + it * 64] = va.x;
            As[aCol + 1][aRow + it * 64] = va.y;
            As[aCol + 2][aRow + it * 64] = va.z;
            As[aCol + 3][aRow + it * 64] = va.w;
        }
#pragma unroll
        for (int it = 0; it < 2; it++) {
            *(float4*)&Bs[bRow + it * 8][bCol] =
                *(const float4*)(Bm + (size_t)(k0 + bRow + it * 8) * N + colBase + bCol);
        }
        __syncthreads();

#pragma unroll
        for (int kk = 0; kk < BK; kk++) {
            float ra[8], rb[8];
#pragma unroll
            for (int i = 0; i < 8; i++) ra[i] = As[kk][ty * 8 + i];
#pragma unroll
            for (int j = 0; j < 8; j++) rb[j] = Bs[kk][tx * 8 + j];
#pragma unroll
            for (int i = 0; i < 8; i++)
#pragma unroll
                for (int j = 0; j < 8; j++) acc[i][j] += ra[i] * rb[j];
        }
        __syncthreads();
    }

    const int r0 = rowBase + ty * 8;
    const int c0 = colBase + tx * 8;
#pragma unroll
    for (int i = 0; i < 8; i++) {
        int r = r0 + i;
        size_t dstRow;
        if (MODE == 1) {
            int bb  = r / 3136;  int rr = r - bb * 3136;
            int win = rr / NTOK; int n  = rr - win * NTOK;
            int ih  = (win >> 3) * 7 + n / 7;
            int iw  = (win & 7) * 7 + n % 7;
            int h = ih + 3; if (h >= 56) h -= 56;
            int w = iw + 3; if (w >= 56) w -= 56;
            dstRow = ((size_t)bb * 3136 + h * 56 + w) * (size_t)N;
        } else {
            dstRow = (size_t)r * (size_t)N;
        }
#pragma unroll
        for (int j = 0; j < 8; j += 4) {
            int c = c0 + j;
            float4 bv = *(const float4*)(bias + c);
            float4 o;
            o.x = acc[i][j + 0] + bv.x;
            o.y = acc[i][j + 1] + bv.y;
            o.z = acc[i][j + 2] + bv.z;
            o.w = acc[i][j + 3] + bv.w;
            if (MODE == 1) {
                float4 xv = *(const float4*)(X + dstRow + c);
                o.x += xv.x; o.y += xv.y; o.z += xv.z; o.w += xv.w;
            }
            if (MODE == 2) {
                o.x = gelu_exact(o.x); o.y = gelu_exact(o.y);
                o.z = gelu_exact(o.z); o.w = gelu_exact(o.w);
            }
            if (MODE == 3) {
                float4 cv = *(const float4*)(C + dstRow + c);
                o.x = cv.x + gelu_exact(o.x);
                o.y = cv.y + gelu_exact(o.y);
                o.z = cv.z + gelu_exact(o.z);
                o.w = cv.w + gelu_exact(o.w);
            }
            *(float4*)(C + dstRow + c) = o;
        }
    }
}

// ---------------------------------------------------------------------------
extern "C" void kernel_launch(void* const* d_in, const int* in_sizes, int n_in,
                              void* d_out, int out_size)
{
    (void)in_sizes; (void)n_in; (void)out_size;

    const float* x     = (const float*)d_in[0];
    const float* ln1g  = (const float*)d_in[1];
    const float* ln1b  = (const float*)d_in[2];
    const float* qkvw  = (const float*)d_in[3];
    const float* qkvb  = (const float*)d_in[4];
    const float* relb  = (const float*)d_in[5];
    const float* projw = (const float*)d_in[6];
    const float* projb = (const float*)d_in[7];
    const float* ln2g  = (const float*)d_in[8];
    const float* ln2b  = (const float*)d_in[9];
    const float* fc1w  = (const float*)d_in[10];
    const float* fc1b  = (const float*)d_in[11];
    const float* fc2w  = (const float*)d_in[12];
    const float* fc2b  = (const float*)d_in[13];
    float* out = (float*)d_out;

    float *ywin, *qkv, *attn, *hbuf;
    cudaGetSymbolAddress((void**)&ywin, g_ywin);
    cudaGetSymbolAddress((void**)&qkv,  g_qkv);
    cudaGetSymbolAddress((void**)&attn, g_attn);
    cudaGetSymbolAddress((void**)&hbuf, g_h);

    // 1) LN1 + shift + window partition
    ln_kernel<true><<<M_ROWS / 8, 256>>>(x, ln1g, ln1b, ywin);

    // 2) QKV GEMM: (100352,384)@(384,1152)
    sgemm_kernel<0><<<dim3(1152 / 128, M_ROWS / 128), 256>>>(
        ywin, qkvw, qkvb, qkv, nullptr, M_ROWS, 1152, 384);

    // 3) windowed attention
    attn_kernel<<<dim3(M_ROWS / NTOK, NHEADS), 256>>>(qkv, relb, attn);

    // 4) proj GEMM + window reverse + roll back + residual  -> d_out = x1
    sgemm_kernel<1><<<dim3(384 / 128, M_ROWS / 128), 256>>>(
        attn, projw, projb, out, x, M_ROWS, 384, 384);

    // 5) LN2 (reads d_out, reuses ywin scratch)
    ln_kernel<false><<<M_ROWS / 8, 256>>>(out, ln2g, ln2b, ywin);

    // 6) FC1 GEMM + exact GELU: (100352,384)@(384,1536)
    sgemm_kernel<2><<<dim3(1536 / 128, M_ROWS / 128), 256>>>(
        ywin, fc1w, fc1b, hbuf, nullptr, M_ROWS, 1536, 384);

    // 7) FC2 GEMM + exact GELU + residual accumulate into d_out
    sgemm_kernel<3><<<dim3(384 / 128, M_ROWS / 128), 256>>>(
        hbuf, fc2w, fc2b, out, nullptr, M_ROWS, 384, 1536);
}